// round 6
// baseline (speedup 1.0000x reference)
#include <cuda_runtime.h>
#include <cuda_bf16.h>
#include <cstdint>

// ---------------------------------------------------------------------------
// FMoELinearProj via legacy HMMA (mma.sync.m16n8k16.bf16).
// fp32 emulated as bf16 2-term split: hi*hi + hi*lo + lo*hi (3 MMAs).
// Operands pre-split into persistent bf16 hi/lo arrays (one elementwise pass
// per call); GEMM mainloop is a 3-stage cp.async pipeline with zero
// per-element ALU. GEMM1 emits y directly in split form for GEMM2.
// CTA tile 128x128, K-tile 32 fp32 (64B bf16 rows), 8 warps (32x64 each).
// R5 fix: SPLIT_OUT epilogue index now includes n0 (R4 dropped it).
// ---------------------------------------------------------------------------

#define BM 128
#define BN 128
#define NTH 256
#define SROW 80                       // padded smem row (64B data + 16B pad)
#define TILEB (128 * SROW)            // 10240 B per bf16 tile
#define STAGEB (4 * TILEB)            // Ahi, Alo, Bhi, Blo
#define NSTAGE 3
#define BIAS_OFF (NSTAGE * STAGEB)    // 122880
#define SMEM_TOTAL (BIAS_OFF + 512)

__device__ int  g_off[65];
__device__ int2 g_tiles[1024];
__device__ int  g_ntiles;

// Persistent split operand storage (sized for this problem's fixed shapes).
__device__ __nv_bfloat16 g_whi[16ull * 4096 * 1024];
__device__ __nv_bfloat16 g_wlo[16ull * 4096 * 1024];
__device__ __nv_bfloat16 g_chi[16ull * 512 * 4096];
__device__ __nv_bfloat16 g_clo[16ull * 512 * 4096];
__device__ __nv_bfloat16 g_xhi[8192ull * 1024];
__device__ __nv_bfloat16 g_xlo[8192ull * 1024];
__device__ __nv_bfloat16 g_yhi[8192ull * 4096];
__device__ __nv_bfloat16 g_ylo[8192ull * 4096];

// ------------------------------- helpers -----------------------------------
__device__ __forceinline__ uint32_t smem_u32(const void* p) {
    uint32_t a;
    asm("{ .reg .u64 t; cvta.to.shared.u64 t, %1; cvt.u32.u64 %0, t; }"
        : "=r"(a) : "l"(p));
    return a;
}
__device__ __forceinline__ void ldsm4(uint32_t* r, uint32_t addr) {
    asm volatile("ldmatrix.sync.aligned.m8n8.x4.shared.b16 {%0,%1,%2,%3}, [%4];"
                 : "=r"(r[0]), "=r"(r[1]), "=r"(r[2]), "=r"(r[3]) : "r"(addr));
}
__device__ __forceinline__ void mma16816(float* c, const uint32_t* a,
                                         const uint32_t* b) {
    asm volatile(
        "mma.sync.aligned.m16n8k16.row.col.f32.bf16.bf16.f32 "
        "{%0,%1,%2,%3}, {%4,%5,%6,%7}, {%8,%9}, {%0,%1,%2,%3};"
        : "+f"(c[0]), "+f"(c[1]), "+f"(c[2]), "+f"(c[3])
        : "r"(a[0]), "r"(a[1]), "r"(a[2]), "r"(a[3]), "r"(b[0]), "r"(b[1]));
}
__device__ __forceinline__ void cpa16(uint32_t dst, const void* src,
                                      uint32_t ssize) {
    asm volatile("cp.async.cg.shared.global [%0], [%1], 16, %2;"
                 :: "r"(dst), "l"(src), "r"(ssize) : "memory");
}
#define CP_COMMIT() asm volatile("cp.async.commit_group;" ::: "memory")
#define CP_WAIT(n)  asm volatile("cp.async.wait_group %0;" :: "n"(n) : "memory")

__device__ __forceinline__ float trunc16f(float a) {
    return __uint_as_float(__float_as_uint(a) & 0xFFFF0000u);
}
__device__ __forceinline__ uint32_t prmt_hi(float a, float b) {
    uint32_t d;
    asm("prmt.b32 %0, %1, %2, 0x7632;" : "=r"(d)
        : "r"(__float_as_uint(a)), "r"(__float_as_uint(b)));
    return d;
}
__device__ __forceinline__ uint32_t pack_lo(float e0, float e1) {
    uint32_t d;
    asm("cvt.rn.bf16x2.f32 %0, %1, %2;" : "=r"(d) : "f"(e1), "f"(e0));
    return d;
}

// ------------------------------ split prepass ------------------------------
__global__ void split_kernel(const float* __restrict__ src,
                             __nv_bfloat16* __restrict__ hi,
                             __nv_bfloat16* __restrict__ lo, long n) {
    long stride = (long)gridDim.x * blockDim.x * 4;
    for (long i = ((long)blockIdx.x * blockDim.x + threadIdx.x) * 4; i < n;
         i += stride) {
        float4 v = *(const float4*)(src + i);
        uint2 h, l;
        h.x = prmt_hi(v.x, v.y);
        h.y = prmt_hi(v.z, v.w);
        l.x = pack_lo(v.x - trunc16f(v.x), v.y - trunc16f(v.y));
        l.y = pack_lo(v.z - trunc16f(v.z), v.w - trunc16f(v.w));
        *(uint2*)(hi + i) = h;
        *(uint2*)(lo + i) = l;
    }
}

// ------------------------------ setup kernel -------------------------------
__global__ void setup_kernel(const int* __restrict__ counts, int E) {
    if (threadIdx.x == 0 && blockIdx.x == 0) {
        int off = 0, nt = 0;
        for (int e = 0; e < E; ++e) {
            g_off[e] = off;
            int c = counts[e];
            for (int m = 0; m < c; m += BM) { g_tiles[nt].x = e; g_tiles[nt].y = m; ++nt; }
            off += c;
        }
        g_off[E] = off;
        g_ntiles = nt;
    }
}

// ------------------------------ main GEMM kernel ---------------------------
// C[row, n] = sum_k A[row, k] * B[e, n, k] (+ bias).
// SPLIT_OUT: write C as split bf16 into g_yhi/g_ylo; else fp32 to Cf.
template <bool ADD_BIAS, bool SPLIT_OUT>
__global__ __launch_bounds__(NTH, 1)
void moe_hmma(const __nv_bfloat16* __restrict__ Ahi,
              const __nv_bfloat16* __restrict__ Alo,
              const __nv_bfloat16* __restrict__ Bhi,
              const __nv_bfloat16* __restrict__ Blo,
              const float* __restrict__ bias, float* __restrict__ Cf,
              int K, int N)
{
    const int tile = blockIdx.y;
    if (tile >= g_ntiles) return;
    const int e    = g_tiles[tile].x;
    const int m0   = g_tiles[tile].y;
    const int row0 = g_off[e] + m0;
    int mrows = g_off[e + 1] - g_off[e] - m0;
    if (mrows > BM) mrows = BM;
    const int n0 = blockIdx.x * BN;

    extern __shared__ char smem[];
    const uint32_t sb = smem_u32(smem);
    const int tid = threadIdx.x, wid = tid >> 5, lane = tid & 31;
    const int warp_m = wid & 3, warp_n = wid >> 2;

    if (ADD_BIAS && tid < 32)
        ((float4*)(smem + BIAS_OFF))[tid] =
            *(const float4*)&bias[(size_t)e * N + n0 + tid * 4];

    // ---- cp.async source/dst precompute: 8 x 16B chunks per thread per kt --
    const size_t Kb = (size_t)K * 2;   // bytes per row in bf16 arrays
    const int id0 = tid, id1 = tid + 256;
    const int r0 = id0 >> 2, r1 = id1 >> 2;
    const uint32_t c0 = (id0 & 3) * 16, c1 = (id1 & 3) * 16;

    const char* src[8];
    uint32_t dst[8], sz[8];
    src[0] = (const char*)Ahi + (size_t)(row0 + r0) * Kb + c0;
    src[1] = (const char*)Ahi + (size_t)(row0 + r1) * Kb + c1;
    src[2] = (const char*)Alo + (size_t)(row0 + r0) * Kb + c0;
    src[3] = (const char*)Alo + (size_t)(row0 + r1) * Kb + c1;
    src[4] = (const char*)Bhi + ((size_t)e * N + n0 + r0) * Kb + c0;
    src[5] = (const char*)Bhi + ((size_t)e * N + n0 + r1) * Kb + c1;
    src[6] = (const char*)Blo + ((size_t)e * N + n0 + r0) * Kb + c0;
    src[7] = (const char*)Blo + ((size_t)e * N + n0 + r1) * Kb + c1;
    dst[0] = (uint32_t)(r0 * SROW) + c0;
    dst[1] = (uint32_t)(r1 * SROW) + c1;
    dst[2] = dst[0] + TILEB;          dst[3] = dst[1] + TILEB;
    dst[4] = dst[0] + 2 * TILEB;      dst[5] = dst[1] + 2 * TILEB;
    dst[6] = dst[0] + 3 * TILEB;      dst[7] = dst[1] + 3 * TILEB;
    sz[0] = (r0 < mrows) ? 16u : 0u;  sz[1] = (r1 < mrows) ? 16u : 0u;
    sz[2] = sz[0];                    sz[3] = sz[1];
    sz[4] = sz[5] = sz[6] = sz[7] = 16u;

#define ISSUE(kt_, slot_) do {                                              \
    const uint32_t stg_ = sb + (uint32_t)(slot_) * STAGEB;                  \
    const size_t ko_ = (size_t)(kt_) * 64;                                  \
    _Pragma("unroll")                                                       \
    for (int i_ = 0; i_ < 8; ++i_)                                          \
        cpa16(stg_ + dst[i_], src[i_] + ko_, sz[i_]);                       \
    CP_COMMIT(); } while (0)

    const int nk = K >> 5;
    ISSUE(0, 0);
    if (nk > 1) ISSUE(1, 1);

    float acc[2][8][4];
#pragma unroll
    for (int mi = 0; mi < 2; ++mi)
#pragma unroll
        for (int nj = 0; nj < 8; ++nj)
#pragma unroll
            for (int q = 0; q < 4; ++q) acc[mi][nj][q] = 0.f;

    const uint32_t a_off = (uint32_t)(warp_m * 32 + (lane & 15)) * SROW +
                           ((lane >> 4) * 16);
    const uint32_t b_off = (uint32_t)(warp_n * 64 + (lane & 7) +
                                      ((lane >> 4) & 1) * 8) * SROW +
                           (((lane >> 3) & 1) * 16);

    int slot = 0;
    for (int kt = 0; kt < nk; ++kt) {
        if (kt + 1 < nk) { CP_WAIT(1); } else { CP_WAIT(0); }
        __syncthreads();
        if (kt + 2 < nk) {
            int ns = slot + 2; if (ns >= NSTAGE) ns -= NSTAGE;
            ISSUE(kt + 2, ns);
        }
        const uint32_t stg = sb + (uint32_t)slot * STAGEB;
#pragma unroll
        for (int k16 = 0; k16 < 2; ++k16) {
            const uint32_t kb = k16 * 32;
            uint32_t ah[2][4], al[2][4], bh[4][4], bl[4][4];
            ldsm4(ah[0], stg + a_off + kb);
            ldsm4(ah[1], stg + a_off + kb + 16 * SROW);
            ldsm4(al[0], stg + TILEB + a_off + kb);
            ldsm4(al[1], stg + TILEB + a_off + kb + 16 * SROW);
#pragma unroll
            for (int bj = 0; bj < 4; ++bj) {
                ldsm4(bh[bj], stg + 2 * TILEB + b_off + kb + bj * 16 * SROW);
                ldsm4(bl[bj], stg + 3 * TILEB + b_off + kb + bj * 16 * SROW);
            }
#pragma unroll
            for (int mi = 0; mi < 2; ++mi)
#pragma unroll
                for (int nj = 0; nj < 8; ++nj)
                    mma16816(acc[mi][nj], ah[mi], &bh[nj >> 1][(nj & 1) * 2]);
#pragma unroll
            for (int mi = 0; mi < 2; ++mi)
#pragma unroll
                for (int nj = 0; nj < 8; ++nj)
                    mma16816(acc[mi][nj], al[mi], &bh[nj >> 1][(nj & 1) * 2]);
#pragma unroll
            for (int mi = 0; mi < 2; ++mi)
#pragma unroll
                for (int nj = 0; nj < 8; ++nj)
                    mma16816(acc[mi][nj], ah[mi], &bl[nj >> 1][(nj & 1) * 2]);
        }
        __syncthreads();
        if (++slot >= NSTAGE) slot = 0;
    }
#undef ISSUE

    // ------------------------------ epilogue --------------------------------
    const float* bs = (const float*)(smem + BIAS_OFF);
    uint32_t* yh32 = (uint32_t*)g_yhi;
    uint32_t* yl32 = (uint32_t*)g_ylo;
#pragma unroll
    for (int mi = 0; mi < 2; ++mi) {
        const int r = warp_m * 32 + mi * 16 + (lane >> 2);
#pragma unroll
        for (int nj = 0; nj < 8; ++nj) {
            const int c = warp_n * 64 + nj * 8 + (lane & 3) * 2;
            float2 v0 = make_float2(acc[mi][nj][0], acc[mi][nj][1]);
            float2 v1 = make_float2(acc[mi][nj][2], acc[mi][nj][3]);
            if (ADD_BIAS) {
                const float b0 = bs[c], b1 = bs[c + 1];
                v0.x += b0; v0.y += b1;
                v1.x += b0; v1.y += b1;
            }
            if (SPLIT_OUT) {
                if (r < mrows) {
                    const size_t ix =
                        ((size_t)(row0 + r) * N + n0 + c) >> 1;   // R5: + n0
                    yh32[ix] = prmt_hi(v0.x, v0.y);
                    yl32[ix] = pack_lo(v0.x - trunc16f(v0.x),
                                       v0.y - trunc16f(v0.y));
                }
                if (r + 8 < mrows) {
                    const size_t ix =
                        ((size_t)(row0 + r + 8) * N + n0 + c) >> 1;  // R5: + n0
                    yh32[ix] = prmt_hi(v1.x, v1.y);
                    yl32[ix] = pack_lo(v1.x - trunc16f(v1.x),
                                       v1.y - trunc16f(v1.y));
                }
            } else {
                if (r < mrows)
                    *(float2*)&Cf[(size_t)(row0 + r) * N + n0 + c] = v0;
                if (r + 8 < mrows)
                    *(float2*)&Cf[(size_t)(row0 + r + 8) * N + n0 + c] = v1;
            }
        }
    }
}

// ------------------------------- launch -------------------------------------
extern "C" void kernel_launch(void* const* d_in, const int* in_sizes, int n_in,
                              void* d_out, int out_size) {
    const float* inp  = (const float*)d_in[0];
    const int*   cnt  = (const int*)  d_in[1];
    const float* wgt  = (const float*)d_in[2];
    const float* bias = (const float*)d_in[3];
    const float* comp = (const float*)d_in[4];
    float* out = (float*)d_out;

    const int E     = in_sizes[1];
    const int D_out = in_sizes[3] / E;
    const int D_in  = in_sizes[2] / in_sizes[3];
    const int T     = in_sizes[0] / D_in;
    const int S     = in_sizes[4] / in_sizes[3];
    const int maxtiles = T / BM + E;

    cudaFuncSetAttribute(moe_hmma<true, true>,
                         cudaFuncAttributeMaxDynamicSharedMemorySize, SMEM_TOTAL);
    cudaFuncSetAttribute(moe_hmma<false, false>,
                         cudaFuncAttributeMaxDynamicSharedMemorySize, SMEM_TOTAL);

    __nv_bfloat16 *whi, *wlo, *chi, *clo, *xhi, *xlo, *yhi, *ylo;
    cudaGetSymbolAddress((void**)&whi, g_whi);
    cudaGetSymbolAddress((void**)&wlo, g_wlo);
    cudaGetSymbolAddress((void**)&chi, g_chi);
    cudaGetSymbolAddress((void**)&clo, g_clo);
    cudaGetSymbolAddress((void**)&xhi, g_xhi);
    cudaGetSymbolAddress((void**)&xlo, g_xlo);
    cudaGetSymbolAddress((void**)&yhi, g_yhi);
    cudaGetSymbolAddress((void**)&ylo, g_ylo);

    setup_kernel<<<1, 1>>>(cnt, E);
    split_kernel<<<592, 256>>>(wgt,  whi, wlo, (long)in_sizes[2]);
    split_kernel<<<592, 256>>>(comp, chi, clo, (long)in_sizes[4]);
    split_kernel<<<296, 256>>>(inp,  xhi, xlo, (long)in_sizes[0]);

    // GEMM1: y = x @ W^T + b  (emitted as split bf16)
    moe_hmma<true, true><<<dim3(D_out / BN, maxtiles), NTH, SMEM_TOTAL>>>(
        xhi, xlo, whi, wlo, bias, nullptr, D_in, D_out);
    // GEMM2: out = y @ C^T  (fp32 out)
    moe_hmma<false, false><<<dim3(S / BN, maxtiles), NTH, SMEM_TOTAL>>>(
        yhi, ylo, chi, clo, nullptr, out, D_out, S);
}

// round 7
// speedup vs baseline: 1.2332x; 1.2332x over previous
#include <cuda_runtime.h>
#include <cuda_bf16.h>
#include <cstdint>

// ---------------------------------------------------------------------------
// FMoELinearProj via legacy HMMA (mma.sync.m16n8k16.bf16).
// fp32 emulated as bf16 2-term split: hi*hi + hi*lo + lo*hi (3 MMAs).
// R6: no prepass — operands split in-loop (hidden under tensor pipe, proven
// R3); GEMM1 emits y pre-split (proven R5); GEMM2 pulls A via cp.async.
// CTA 128x128, 512 threads (16 warps, 32x32 warp tile), 2-stage smem,
// one __syncthreads per k-tile.
// ---------------------------------------------------------------------------

#define BM 128
#define BN 128
#define NTH 512
#define SROW 80                       // padded smem row (64B data + 16B pad)
#define TILEB (128 * SROW)            // 10240 B per bf16 tile
#define STAGEB (4 * TILEB)            // Ahi, Alo, Bhi, Blo
#define BIAS_OFF (2 * STAGEB)         // 81920
#define SMEM_TOTAL (BIAS_OFF + 512)

__device__ int  g_off[65];
__device__ int2 g_tiles[1024];
__device__ int  g_ntiles;
__device__ __nv_bfloat16 g_yhi[8192ull * 4096];
__device__ __nv_bfloat16 g_ylo[8192ull * 4096];

// ------------------------------- helpers -----------------------------------
__device__ __forceinline__ uint32_t smem_u32(const void* p) {
    uint32_t a;
    asm("{ .reg .u64 t; cvta.to.shared.u64 t, %1; cvt.u32.u64 %0, t; }"
        : "=r"(a) : "l"(p));
    return a;
}
__device__ __forceinline__ void ldsm4(uint32_t* r, uint32_t addr) {
    asm volatile("ldmatrix.sync.aligned.m8n8.x4.shared.b16 {%0,%1,%2,%3}, [%4];"
                 : "=r"(r[0]), "=r"(r[1]), "=r"(r[2]), "=r"(r[3]) : "r"(addr));
}
__device__ __forceinline__ void mma16816(float* c, const uint32_t* a,
                                         const uint32_t* b) {
    asm volatile(
        "mma.sync.aligned.m16n8k16.row.col.f32.bf16.bf16.f32 "
        "{%0,%1,%2,%3}, {%4,%5,%6,%7}, {%8,%9}, {%0,%1,%2,%3};"
        : "+f"(c[0]), "+f"(c[1]), "+f"(c[2]), "+f"(c[3])
        : "r"(a[0]), "r"(a[1]), "r"(a[2]), "r"(a[3]), "r"(b[0]), "r"(b[1]));
}
__device__ __forceinline__ void cpa16(uint32_t dst, const void* src,
                                      uint32_t ssize) {
    asm volatile("cp.async.cg.shared.global [%0], [%1], 16, %2;"
                 :: "r"(dst), "l"(src), "r"(ssize) : "memory");
}
#define CP_COMMIT() asm volatile("cp.async.commit_group;" ::: "memory")
#define CP_WAIT0()  asm volatile("cp.async.wait_group 0;" ::: "memory")

__device__ __forceinline__ void sts128(uint32_t a, uint32_t r0, uint32_t r1,
                                       uint32_t r2, uint32_t r3) {
    asm volatile("st.shared.v4.b32 [%0], {%1, %2, %3, %4};"
                 :: "r"(a), "r"(r0), "r"(r1), "r"(r2), "r"(r3) : "memory");
}
__device__ __forceinline__ float trunc16f(float a) {
    return __uint_as_float(__float_as_uint(a) & 0xFFFF0000u);
}
__device__ __forceinline__ uint32_t prmt_hi(float a, float b) {
    uint32_t d;
    asm("prmt.b32 %0, %1, %2, 0x7632;" : "=r"(d)
        : "r"(__float_as_uint(a)), "r"(__float_as_uint(b)));
    return d;
}
__device__ __forceinline__ uint32_t pack_lo(float e0, float e1) {
    uint32_t d;
    asm("cvt.rn.bf16x2.f32 %0, %1, %2;" : "=r"(d) : "f"(e1), "f"(e0));
    return d;
}
// Split 8 consecutive fp32 (2 float4) into 16B bf16 hi + 16B bf16 lo, store.
__device__ __forceinline__ void split_sts(uint32_t hib, uint32_t lob,
                                          float4 u0, float4 u1) {
    uint32_t h0 = prmt_hi(u0.x, u0.y);
    uint32_t h1 = prmt_hi(u0.z, u0.w);
    uint32_t h2 = prmt_hi(u1.x, u1.y);
    uint32_t h3 = prmt_hi(u1.z, u1.w);
    uint32_t l0 = pack_lo(u0.x - trunc16f(u0.x), u0.y - trunc16f(u0.y));
    uint32_t l1 = pack_lo(u0.z - trunc16f(u0.z), u0.w - trunc16f(u0.w));
    uint32_t l2 = pack_lo(u1.x - trunc16f(u1.x), u1.y - trunc16f(u1.y));
    uint32_t l3 = pack_lo(u1.z - trunc16f(u1.z), u1.w - trunc16f(u1.w));
    sts128(hib, h0, h1, h2, h3);
    sts128(lob, l0, l1, l2, l3);
}

// ------------------------------ setup kernel -------------------------------
__global__ void setup_kernel(const int* __restrict__ counts, int E) {
    if (threadIdx.x == 0 && blockIdx.x == 0) {
        int off = 0, nt = 0;
        for (int e = 0; e < E; ++e) {
            g_off[e] = off;
            int c = counts[e];
            for (int m = 0; m < c; m += BM) { g_tiles[nt].x = e; g_tiles[nt].y = m; ++nt; }
            off += c;
        }
        g_off[E] = off;
        g_ntiles = nt;
    }
}

// ------------------------------ main GEMM kernel ---------------------------
// C[row, n] = sum_k A[row, k] * B[e, n, k] (+ bias).
// A_BF16: A comes pre-split (g_yhi/g_ylo) via cp.async; else fp32 in-loop split.
// SPLIT_OUT: write C split bf16 into g_yhi/g_ylo; else fp32 to Cf.
template <bool ADD_BIAS, bool A_BF16, bool SPLIT_OUT>
__global__ __launch_bounds__(NTH, 1)
void moe_hmma(const float* __restrict__ Af,
              const __nv_bfloat16* __restrict__ Ahi,
              const __nv_bfloat16* __restrict__ Alo,
              const float* __restrict__ Bf,
              const float* __restrict__ bias, float* __restrict__ Cf,
              int K, int N)
{
    const int tile = blockIdx.y;
    if (tile >= g_ntiles) return;
    const int e    = g_tiles[tile].x;
    const int m0   = g_tiles[tile].y;
    const int row0 = g_off[e] + m0;
    int mrows = g_off[e + 1] - g_off[e] - m0;
    if (mrows > BM) mrows = BM;
    const int n0 = blockIdx.x * BN;

    extern __shared__ char smem[];
    const uint32_t sb = smem_u32(smem);
    const int tid = threadIdx.x, wid = tid >> 5, lane = tid & 31;
    const int warp_m = wid & 3, warp_n = wid >> 2;

    if (ADD_BIAS && tid < 32)
        ((float4*)(smem + BIAS_OFF))[tid] =
            *(const float4*)&bias[(size_t)e * N + n0 + tid * 4];

    // ---- load mapping: 512 threads, one 8-fp32 chunk of A and of B each ----
    const int crow = tid >> 2;                 // 0..127
    const int ccol = (tid & 3) * 8;            // fp32 offset in k-tile
    const uint32_t sdst = (uint32_t)(crow * SROW) + (tid & 3) * 16;
    const bool aok = crow < mrows;
    const float4 z4 = make_float4(0.f, 0.f, 0.f, 0.f);

    const float* Afp = Af + (size_t)(row0 + crow) * K + ccol;           // fp32 A
    const char*  Ahp = (const char*)(Ahi + (size_t)(row0 + crow) * K + ccol);
    const char*  Alp = (const char*)(Alo + (size_t)(row0 + crow) * K + ccol);
    const float* Bfp = Bf + ((size_t)e * N + n0 + crow) * K + ccol;
    const uint32_t acp_sz = aok ? 16u : 0u;

    float4 av0, av1, bv0, bv1;

    // -------- prologue: stage kt=0 into buffer 0 --------
    if (A_BF16) {
        cpa16(sb + sdst, Ahp, acp_sz);
        cpa16(sb + TILEB + sdst, Alp, acp_sz);
        CP_COMMIT();
    } else {
        av0 = aok ? *(const float4*)Afp : z4;
        av1 = aok ? *(const float4*)(Afp + 4) : z4;
    }
    bv0 = *(const float4*)Bfp;
    bv1 = *(const float4*)(Bfp + 4);
    if (!A_BF16) split_sts(sb + sdst, sb + TILEB + sdst, av0, av1);
    split_sts(sb + 2 * TILEB + sdst, sb + 3 * TILEB + sdst, bv0, bv1);
    if (A_BF16) CP_WAIT0();
    __syncthreads();

    float acc[2][4][4];
#pragma unroll
    for (int mi = 0; mi < 2; ++mi)
#pragma unroll
        for (int nj = 0; nj < 4; ++nj)
#pragma unroll
            for (int q = 0; q < 4; ++q) acc[mi][nj][q] = 0.f;

    const uint32_t a_off = (uint32_t)(warp_m * 32 + (lane & 15)) * SROW +
                           ((lane >> 4) * 16);
    const uint32_t b_off = (uint32_t)(warp_n * 32 + (lane & 7) +
                                      ((lane >> 4) & 1) * 8) * SROW +
                           (((lane >> 3) & 1) * 16);

    const int nk = K >> 5;
    for (int kt = 0; kt < nk; ++kt) {
        const uint32_t stg  = sb + (uint32_t)(kt & 1) * STAGEB;
        const uint32_t nstg = sb + (uint32_t)((kt + 1) & 1) * STAGEB;
        const bool more = (kt + 1 < nk);
        if (more) {
            const int ko = (kt + 1) * 32;
            if (A_BF16) {
                cpa16(nstg + sdst, Ahp + ko * 2, acp_sz);
                cpa16(nstg + TILEB + sdst, Alp + ko * 2, acp_sz);
                CP_COMMIT();
            } else {
                av0 = aok ? *(const float4*)(Afp + ko) : z4;
                av1 = aok ? *(const float4*)(Afp + ko + 4) : z4;
            }
            bv0 = *(const float4*)(Bfp + ko);
            bv1 = *(const float4*)(Bfp + ko + 4);
        }
#pragma unroll
        for (int k16 = 0; k16 < 2; ++k16) {
            const uint32_t kb = k16 * 32;
            uint32_t ah[2][4], al[2][4], bh[2][4], bl[2][4];
            ldsm4(ah[0], stg + a_off + kb);
            ldsm4(ah[1], stg + a_off + kb + 16 * SROW);
            ldsm4(al[0], stg + TILEB + a_off + kb);
            ldsm4(al[1], stg + TILEB + a_off + kb + 16 * SROW);
            ldsm4(bh[0], stg + 2 * TILEB + b_off + kb);
            ldsm4(bh[1], stg + 2 * TILEB + b_off + kb + 16 * SROW);
            ldsm4(bl[0], stg + 3 * TILEB + b_off + kb);
            ldsm4(bl[1], stg + 3 * TILEB + b_off + kb + 16 * SROW);
#pragma unroll
            for (int mi = 0; mi < 2; ++mi)
#pragma unroll
                for (int nj = 0; nj < 4; ++nj)
                    mma16816(acc[mi][nj], ah[mi], &bh[nj >> 1][(nj & 1) * 2]);
#pragma unroll
            for (int mi = 0; mi < 2; ++mi)
#pragma unroll
                for (int nj = 0; nj < 4; ++nj)
                    mma16816(acc[mi][nj], al[mi], &bh[nj >> 1][(nj & 1) * 2]);
#pragma unroll
            for (int mi = 0; mi < 2; ++mi)
#pragma unroll
                for (int nj = 0; nj < 4; ++nj)
                    mma16816(acc[mi][nj], ah[mi], &bl[nj >> 1][(nj & 1) * 2]);
        }
        if (more) {
            if (!A_BF16)
                split_sts(nstg + sdst, nstg + TILEB + sdst, av0, av1);
            split_sts(nstg + 2 * TILEB + sdst, nstg + 3 * TILEB + sdst,
                      bv0, bv1);
            if (A_BF16) CP_WAIT0();
        }
        __syncthreads();
    }

    // ------------------------------ epilogue --------------------------------
    const float* bs = (const float*)(smem + BIAS_OFF);
    uint32_t* yh32 = (uint32_t*)g_yhi;
    uint32_t* yl32 = (uint32_t*)g_ylo;
#pragma unroll
    for (int mi = 0; mi < 2; ++mi) {
        const int r = warp_m * 32 + mi * 16 + (lane >> 2);
#pragma unroll
        for (int nj = 0; nj < 4; ++nj) {
            const int c = warp_n * 32 + nj * 8 + (lane & 3) * 2;
            float2 v0 = make_float2(acc[mi][nj][0], acc[mi][nj][1]);
            float2 v1 = make_float2(acc[mi][nj][2], acc[mi][nj][3]);
            if (ADD_BIAS) {
                const float b0 = bs[c], b1 = bs[c + 1];
                v0.x += b0; v0.y += b1;
                v1.x += b0; v1.y += b1;
            }
            if (SPLIT_OUT) {
                if (r < mrows) {
                    const size_t ix = ((size_t)(row0 + r) * N + n0 + c) >> 1;
                    yh32[ix] = prmt_hi(v0.x, v0.y);
                    yl32[ix] = pack_lo(v0.x - trunc16f(v0.x),
                                       v0.y - trunc16f(v0.y));
                }
                if (r + 8 < mrows) {
                    const size_t ix = ((size_t)(row0 + r + 8) * N + n0 + c) >> 1;
                    yh32[ix] = prmt_hi(v1.x, v1.y);
                    yl32[ix] = pack_lo(v1.x - trunc16f(v1.x),
                                       v1.y - trunc16f(v1.y));
                }
            } else {
                if (r < mrows)
                    *(float2*)&Cf[(size_t)(row0 + r) * N + n0 + c] = v0;
                if (r + 8 < mrows)
                    *(float2*)&Cf[(size_t)(row0 + r + 8) * N + n0 + c] = v1;
            }
        }
    }
}

// ------------------------------- launch -------------------------------------
extern "C" void kernel_launch(void* const* d_in, const int* in_sizes, int n_in,
                              void* d_out, int out_size) {
    const float* inp  = (const float*)d_in[0];
    const int*   cnt  = (const int*)  d_in[1];
    const float* wgt  = (const float*)d_in[2];
    const float* bias = (const float*)d_in[3];
    const float* comp = (const float*)d_in[4];
    float* out = (float*)d_out;

    const int E     = in_sizes[1];
    const int D_out = in_sizes[3] / E;
    const int D_in  = in_sizes[2] / in_sizes[3];
    const int T     = in_sizes[0] / D_in;
    const int S     = in_sizes[4] / in_sizes[3];
    const int maxtiles = T / BM + E;

    cudaFuncSetAttribute(moe_hmma<true, false, true>,
                         cudaFuncAttributeMaxDynamicSharedMemorySize, SMEM_TOTAL);
    cudaFuncSetAttribute(moe_hmma<false, true, false>,
                         cudaFuncAttributeMaxDynamicSharedMemorySize, SMEM_TOTAL);

    __nv_bfloat16 *yhi, *ylo;
    cudaGetSymbolAddress((void**)&yhi, g_yhi);
    cudaGetSymbolAddress((void**)&ylo, g_ylo);

    setup_kernel<<<1, 1>>>(cnt, E);

    // GEMM1: y = x @ W^T + b  (A fp32 split in-loop; y emitted split bf16)
    moe_hmma<true, false, true><<<dim3(D_out / BN, maxtiles), NTH, SMEM_TOTAL>>>(
        inp, nullptr, nullptr, wgt, bias, nullptr, D_in, D_out);
    // GEMM2: out = y @ C^T  (A pre-split via cp.async; comp split in-loop)
    moe_hmma<false, true, false><<<dim3(S / BN, maxtiles), NTH, SMEM_TOTAL>>>(
        nullptr, yhi, ylo, comp, nullptr, out, D_out, S);
}

// round 8
// speedup vs baseline: 1.2467x; 1.0109x over previous
#include <cuda_runtime.h>
#include <cuda_bf16.h>
#include <cstdint>

// ---------------------------------------------------------------------------
// FMoELinearProj via legacy HMMA (mma.sync.m16n8k16.bf16).
// fp32 emulated as bf16 2-term split: hi*hi + hi*lo + lo*hi (3 MMAs).
// R7: R6 plumbing (fused in-loop splits, split-y handoff, cp.async A in
// GEMM2, single sync/kt) with R5's proven warp geometry: 256 threads,
// 8 warps of 32x64 (16 accumulator chains/warp, 4:1 MMA:LDSM).
// ---------------------------------------------------------------------------

#define BM 128
#define BN 128
#define NTH 256
#define SROW 80                       // padded smem row (64B data + 16B pad)
#define TILEB (128 * SROW)            // 10240 B per bf16 tile
#define STAGEB (4 * TILEB)            // Ahi, Alo, Bhi, Blo
#define BIAS_OFF (2 * STAGEB)         // 81920
#define SMEM_TOTAL (BIAS_OFF + 512)

__device__ int  g_off[65];
__device__ int2 g_tiles[1024];
__device__ int  g_ntiles;
__device__ __nv_bfloat16 g_yhi[8192ull * 4096];
__device__ __nv_bfloat16 g_ylo[8192ull * 4096];

// ------------------------------- helpers -----------------------------------
__device__ __forceinline__ uint32_t smem_u32(const void* p) {
    uint32_t a;
    asm("{ .reg .u64 t; cvta.to.shared.u64 t, %1; cvt.u32.u64 %0, t; }"
        : "=r"(a) : "l"(p));
    return a;
}
__device__ __forceinline__ void ldsm4(uint32_t* r, uint32_t addr) {
    asm volatile("ldmatrix.sync.aligned.m8n8.x4.shared.b16 {%0,%1,%2,%3}, [%4];"
                 : "=r"(r[0]), "=r"(r[1]), "=r"(r[2]), "=r"(r[3]) : "r"(addr));
}
__device__ __forceinline__ void mma16816(float* c, const uint32_t* a,
                                         const uint32_t* b) {
    asm volatile(
        "mma.sync.aligned.m16n8k16.row.col.f32.bf16.bf16.f32 "
        "{%0,%1,%2,%3}, {%4,%5,%6,%7}, {%8,%9}, {%0,%1,%2,%3};"
        : "+f"(c[0]), "+f"(c[1]), "+f"(c[2]), "+f"(c[3])
        : "r"(a[0]), "r"(a[1]), "r"(a[2]), "r"(a[3]), "r"(b[0]), "r"(b[1]));
}
__device__ __forceinline__ void cpa16(uint32_t dst, const void* src,
                                      uint32_t ssize) {
    asm volatile("cp.async.cg.shared.global [%0], [%1], 16, %2;"
                 :: "r"(dst), "l"(src), "r"(ssize) : "memory");
}
#define CP_COMMIT() asm volatile("cp.async.commit_group;" ::: "memory")
#define CP_WAIT0()  asm volatile("cp.async.wait_group 0;" ::: "memory")

__device__ __forceinline__ void sts128(uint32_t a, uint32_t r0, uint32_t r1,
                                       uint32_t r2, uint32_t r3) {
    asm volatile("st.shared.v4.b32 [%0], {%1, %2, %3, %4};"
                 :: "r"(a), "r"(r0), "r"(r1), "r"(r2), "r"(r3) : "memory");
}
__device__ __forceinline__ float trunc16f(float a) {
    return __uint_as_float(__float_as_uint(a) & 0xFFFF0000u);
}
__device__ __forceinline__ uint32_t prmt_hi(float a, float b) {
    uint32_t d;
    asm("prmt.b32 %0, %1, %2, 0x7632;" : "=r"(d)
        : "r"(__float_as_uint(a)), "r"(__float_as_uint(b)));
    return d;
}
__device__ __forceinline__ uint32_t pack_lo(float e0, float e1) {
    uint32_t d;
    asm("cvt.rn.bf16x2.f32 %0, %1, %2;" : "=r"(d) : "f"(e1), "f"(e0));
    return d;
}
// Split 8 consecutive fp32 (2 float4) into 16B bf16 hi + 16B bf16 lo, store.
__device__ __forceinline__ void split_sts(uint32_t hib, uint32_t lob,
                                          float4 u0, float4 u1) {
    uint32_t h0 = prmt_hi(u0.x, u0.y);
    uint32_t h1 = prmt_hi(u0.z, u0.w);
    uint32_t h2 = prmt_hi(u1.x, u1.y);
    uint32_t h3 = prmt_hi(u1.z, u1.w);
    uint32_t l0 = pack_lo(u0.x - trunc16f(u0.x), u0.y - trunc16f(u0.y));
    uint32_t l1 = pack_lo(u0.z - trunc16f(u0.z), u0.w - trunc16f(u0.w));
    uint32_t l2 = pack_lo(u1.x - trunc16f(u1.x), u1.y - trunc16f(u1.y));
    uint32_t l3 = pack_lo(u1.z - trunc16f(u1.z), u1.w - trunc16f(u1.w));
    sts128(hib, h0, h1, h2, h3);
    sts128(lob, l0, l1, l2, l3);
}

// ------------------------------ setup kernel -------------------------------
__global__ void setup_kernel(const int* __restrict__ counts, int E) {
    if (threadIdx.x == 0 && blockIdx.x == 0) {
        int off = 0, nt = 0;
        for (int e = 0; e < E; ++e) {
            g_off[e] = off;
            int c = counts[e];
            for (int m = 0; m < c; m += BM) { g_tiles[nt].x = e; g_tiles[nt].y = m; ++nt; }
            off += c;
        }
        g_off[E] = off;
        g_ntiles = nt;
    }
}

// ------------------------------ main GEMM kernel ---------------------------
// C[row, n] = sum_k A[row, k] * B[e, n, k] (+ bias).
// A_BF16: A comes pre-split (g_yhi/g_ylo) via cp.async; else fp32 in-loop split.
// SPLIT_OUT: write C split bf16 into g_yhi/g_ylo; else fp32 to Cf.
template <bool ADD_BIAS, bool A_BF16, bool SPLIT_OUT>
__global__ __launch_bounds__(NTH, 1)
void moe_hmma(const float* __restrict__ Af,
              const __nv_bfloat16* __restrict__ Ahi,
              const __nv_bfloat16* __restrict__ Alo,
              const float* __restrict__ Bf,
              const float* __restrict__ bias, float* __restrict__ Cf,
              int K, int N)
{
    const int tile = blockIdx.y;
    if (tile >= g_ntiles) return;
    const int e    = g_tiles[tile].x;
    const int m0   = g_tiles[tile].y;
    const int row0 = g_off[e] + m0;
    int mrows = g_off[e + 1] - g_off[e] - m0;
    if (mrows > BM) mrows = BM;
    const int n0 = blockIdx.x * BN;

    extern __shared__ char smem[];
    const uint32_t sb = smem_u32(smem);
    const int tid = threadIdx.x, wid = tid >> 5, lane = tid & 31;
    const int warp_m = wid & 3, warp_n = wid >> 2;   // 4 x 2 warp grid

    if (ADD_BIAS && tid < 32)
        ((float4*)(smem + BIAS_OFF))[tid] =
            *(const float4*)&bias[(size_t)e * N + n0 + tid * 4];

    // ---- load mapping: 2 chunks (8 fp32 / 16B-bf16) per thread per tile ----
    const int r0c = tid >> 2;              // rows r0c and r0c+64
    const int ccol = (tid & 3) * 8;        // fp32 column offset in k-tile
    const uint32_t sdst0 = (uint32_t)(r0c * SROW) + (tid & 3) * 16;
    const uint32_t sdst1 = sdst0 + 64 * SROW;
    const bool aok0 = r0c < mrows;
    const bool aok1 = (r0c + 64) < mrows;
    const float4 z4 = make_float4(0.f, 0.f, 0.f, 0.f);

    const float* Afp0 = Af + (size_t)(row0 + r0c) * K + ccol;
    const float* Afp1 = Af + (size_t)(row0 + r0c + 64) * K + ccol;
    const char*  Ahp0 = (const char*)(Ahi + (size_t)(row0 + r0c) * K + ccol);
    const char*  Ahp1 = (const char*)(Ahi + (size_t)(row0 + r0c + 64) * K + ccol);
    const char*  Alp0 = (const char*)(Alo + (size_t)(row0 + r0c) * K + ccol);
    const char*  Alp1 = (const char*)(Alo + (size_t)(row0 + r0c + 64) * K + ccol);
    const float* Bfp0 = Bf + ((size_t)e * N + n0 + r0c) * K + ccol;
    const float* Bfp1 = Bf + ((size_t)e * N + n0 + r0c + 64) * K + ccol;
    const uint32_t sz0 = aok0 ? 16u : 0u, sz1 = aok1 ? 16u : 0u;

    float4 a00, a01, a10, a11, b00, b01, b10, b11;

    // -------- prologue: stage kt=0 into buffer 0 --------
    if (A_BF16) {
        cpa16(sb + sdst0, Ahp0, sz0);
        cpa16(sb + sdst1, Ahp1, sz1);
        cpa16(sb + TILEB + sdst0, Alp0, sz0);
        cpa16(sb + TILEB + sdst1, Alp1, sz1);
        CP_COMMIT();
    } else {
        a00 = aok0 ? *(const float4*)Afp0 : z4;
        a01 = aok0 ? *(const float4*)(Afp0 + 4) : z4;
        a10 = aok1 ? *(const float4*)Afp1 : z4;
        a11 = aok1 ? *(const float4*)(Afp1 + 4) : z4;
    }
    b00 = *(const float4*)Bfp0;
    b01 = *(const float4*)(Bfp0 + 4);
    b10 = *(const float4*)Bfp1;
    b11 = *(const float4*)(Bfp1 + 4);
    if (!A_BF16) {
        split_sts(sb + sdst0, sb + TILEB + sdst0, a00, a01);
        split_sts(sb + sdst1, sb + TILEB + sdst1, a10, a11);
    }
    split_sts(sb + 2 * TILEB + sdst0, sb + 3 * TILEB + sdst0, b00, b01);
    split_sts(sb + 2 * TILEB + sdst1, sb + 3 * TILEB + sdst1, b10, b11);
    if (A_BF16) CP_WAIT0();
    __syncthreads();

    float acc[2][8][4];
#pragma unroll
    for (int mi = 0; mi < 2; ++mi)
#pragma unroll
        for (int nj = 0; nj < 8; ++nj)
#pragma unroll
            for (int q = 0; q < 4; ++q) acc[mi][nj][q] = 0.f;

    const uint32_t a_off = (uint32_t)(warp_m * 32 + (lane & 15)) * SROW +
                           ((lane >> 4) * 16);
    const uint32_t b_off = (uint32_t)(warp_n * 64 + (lane & 7) +
                                      ((lane >> 4) & 1) * 8) * SROW +
                           (((lane >> 3) & 1) * 16);

    const int nk = K >> 5;
    for (int kt = 0; kt < nk; ++kt) {
        const uint32_t stg  = sb + (uint32_t)(kt & 1) * STAGEB;
        const uint32_t nstg = sb + (uint32_t)((kt + 1) & 1) * STAGEB;
        const bool more = (kt + 1 < nk);
        if (more) {
            const int ko = (kt + 1) * 32;
            if (A_BF16) {
                cpa16(nstg + sdst0, Ahp0 + ko * 2, sz0);
                cpa16(nstg + sdst1, Ahp1 + ko * 2, sz1);
                cpa16(nstg + TILEB + sdst0, Alp0 + ko * 2, sz0);
                cpa16(nstg + TILEB + sdst1, Alp1 + ko * 2, sz1);
                CP_COMMIT();
            } else {
                a00 = aok0 ? *(const float4*)(Afp0 + ko) : z4;
                a01 = aok0 ? *(const float4*)(Afp0 + ko + 4) : z4;
                a10 = aok1 ? *(const float4*)(Afp1 + ko) : z4;
                a11 = aok1 ? *(const float4*)(Afp1 + ko + 4) : z4;
            }
            b00 = *(const float4*)(Bfp0 + ko);
            b01 = *(const float4*)(Bfp0 + ko + 4);
            b10 = *(const float4*)(Bfp1 + ko);
            b11 = *(const float4*)(Bfp1 + ko + 4);
        }
#pragma unroll
        for (int k16 = 0; k16 < 2; ++k16) {
            const uint32_t kb = k16 * 32;
            uint32_t ah[2][4], al[2][4], bh[4][4], bl[4][4];
            ldsm4(ah[0], stg + a_off + kb);
            ldsm4(ah[1], stg + a_off + kb + 16 * SROW);
            ldsm4(al[0], stg + TILEB + a_off + kb);
            ldsm4(al[1], stg + TILEB + a_off + kb + 16 * SROW);
#pragma unroll
            for (int bj = 0; bj < 4; ++bj) {
                ldsm4(bh[bj], stg + 2 * TILEB + b_off + kb + bj * 16 * SROW);
                ldsm4(bl[bj], stg + 3 * TILEB + b_off + kb + bj * 16 * SROW);
            }
#pragma unroll
            for (int mi = 0; mi < 2; ++mi)
#pragma unroll
                for (int nj = 0; nj < 8; ++nj)
                    mma16816(acc[mi][nj], ah[mi], &bh[nj >> 1][(nj & 1) * 2]);
#pragma unroll
            for (int mi = 0; mi < 2; ++mi)
#pragma unroll
                for (int nj = 0; nj < 8; ++nj)
                    mma16816(acc[mi][nj], al[mi], &bh[nj >> 1][(nj & 1) * 2]);
#pragma unroll
            for (int mi = 0; mi < 2; ++mi)
#pragma unroll
                for (int nj = 0; nj < 8; ++nj)
                    mma16816(acc[mi][nj], ah[mi], &bl[nj >> 1][(nj & 1) * 2]);
        }
        if (more) {
            if (!A_BF16) {
                split_sts(nstg + sdst0, nstg + TILEB + sdst0, a00, a01);
                split_sts(nstg + sdst1, nstg + TILEB + sdst1, a10, a11);
            }
            split_sts(nstg + 2 * TILEB + sdst0, nstg + 3 * TILEB + sdst0,
                      b00, b01);
            split_sts(nstg + 2 * TILEB + sdst1, nstg + 3 * TILEB + sdst1,
                      b10, b11);
            if (A_BF16) CP_WAIT0();
        }
        __syncthreads();
    }

    // ------------------------------ epilogue --------------------------------
    const float* bs = (const float*)(smem + BIAS_OFF);
    uint32_t* yh32 = (uint32_t*)g_yhi;
    uint32_t* yl32 = (uint32_t*)g_ylo;
#pragma unroll
    for (int mi = 0; mi < 2; ++mi) {
        const int r = warp_m * 32 + mi * 16 + (lane >> 2);
#pragma unroll
        for (int nj = 0; nj < 8; ++nj) {
            const int c = warp_n * 64 + nj * 8 + (lane & 3) * 2;
            float2 v0 = make_float2(acc[mi][nj][0], acc[mi][nj][1]);
            float2 v1 = make_float2(acc[mi][nj][2], acc[mi][nj][3]);
            if (ADD_BIAS) {
                const float b0 = bs[c], b1 = bs[c + 1];
                v0.x += b0; v0.y += b1;
                v1.x += b0; v1.y += b1;
            }
            if (SPLIT_OUT) {
                if (r < mrows) {
                    const size_t ix = ((size_t)(row0 + r) * N + n0 + c) >> 1;
                    yh32[ix] = prmt_hi(v0.x, v0.y);
                    yl32[ix] = pack_lo(v0.x - trunc16f(v0.x),
                                       v0.y - trunc16f(v0.y));
                }
                if (r + 8 < mrows) {
                    const size_t ix = ((size_t)(row0 + r + 8) * N + n0 + c) >> 1;
                    yh32[ix] = prmt_hi(v1.x, v1.y);
                    yl32[ix] = pack_lo(v1.x - trunc16f(v1.x),
                                       v1.y - trunc16f(v1.y));
                }
            } else {
                if (r < mrows)
                    *(float2*)&Cf[(size_t)(row0 + r) * N + n0 + c] = v0;
                if (r + 8 < mrows)
                    *(float2*)&Cf[(size_t)(row0 + r + 8) * N + n0 + c] = v1;
            }
        }
    }
}

// ------------------------------- launch -------------------------------------
extern "C" void kernel_launch(void* const* d_in, const int* in_sizes, int n_in,
                              void* d_out, int out_size) {
    const float* inp  = (const float*)d_in[0];
    const int*   cnt  = (const int*)  d_in[1];
    const float* wgt  = (const float*)d_in[2];
    const float* bias = (const float*)d_in[3];
    const float* comp = (const float*)d_in[4];
    float* out = (float*)d_out;

    const int E     = in_sizes[1];
    const int D_out = in_sizes[3] / E;
    const int D_in  = in_sizes[2] / in_sizes[3];
    const int T     = in_sizes[0] / D_in;
    const int S     = in_sizes[4] / in_sizes[3];
    const int maxtiles = T / BM + E;

    cudaFuncSetAttribute(moe_hmma<true, false, true>,
                         cudaFuncAttributeMaxDynamicSharedMemorySize, SMEM_TOTAL);
    cudaFuncSetAttribute(moe_hmma<false, true, false>,
                         cudaFuncAttributeMaxDynamicSharedMemorySize, SMEM_TOTAL);

    __nv_bfloat16 *yhi, *ylo;
    cudaGetSymbolAddress((void**)&yhi, g_yhi);
    cudaGetSymbolAddress((void**)&ylo, g_ylo);

    setup_kernel<<<1, 1>>>(cnt, E);

    // GEMM1: y = x @ W^T + b  (A fp32 split in-loop; y emitted split bf16)
    moe_hmma<true, false, true><<<dim3(D_out / BN, maxtiles), NTH, SMEM_TOTAL>>>(
        inp, nullptr, nullptr, wgt, bias, nullptr, D_in, D_out);
    // GEMM2: out = y @ C^T  (A pre-split via cp.async; comp split in-loop)
    moe_hmma<false, true, false><<<dim3(S / BN, maxtiles), NTH, SMEM_TOTAL>>>(
        nullptr, yhi, ylo, comp, nullptr, out, D_out, S);
}